// round 13
// baseline (speedup 1.0000x reference)
#include <cuda_runtime.h>
#include <cuda_bf16.h>
#include <cstdint>

#define NN 50000
#define EE 800000
#define ETOT (NN + EE)

// ---------------- scratch (static device globals; no allocation) ----------------
__device__ float4 g_h[NN * 32];     // GEMM output, pre-scaled by dinv[row]  [N,128]
__device__ float4 g_agg[NN * 32];   // aggregated  [N,128]
__device__ __align__(16) int g_cnt[NN];
__device__ float  g_dinv[NN];
__device__ int    g_rowptr[NN + 1];
__device__ int    g_fill[NN];
__device__ int    g_src[ETOT];      // CSR src indices (norm folded into h / output)
__device__ float  g_sum[128], g_sq[128], g_scale[128], g_shift[128];
__device__ int    g_is64;
__device__ int    g_bsum[256], g_boff[256];
__device__ int    g_barrier;
__device__ uint4  g_Bf[3][4096];    // mma fragments [set][kstep(8)][ntile(16)][lane(32)]

// ---------------- bf16 hi/lo helpers ----------------
__device__ __forceinline__ void pack_hilo(float x, float y, uint32_t& h, uint32_t& l) {
    __nv_bfloat162 hb = __floats2bfloat162_rn(x, y);
    float hx = __bfloat162float(hb.x), hy = __bfloat162float(hb.y);
    __nv_bfloat162 lb = __floats2bfloat162_rn(x - hx, y - hy);
    h = *(uint32_t*)&hb;
    l = *(uint32_t*)&lb;
}

// ---------------- k_setup: init + detect + weight fragment pack ----------------
__global__ void __launch_bounds__(256) k_setup(
    const int* __restrict__ ei,
    const float* __restrict__ W1, const float* __restrict__ W2,
    const float* __restrict__ Wmu, const float* __restrict__ Wls, int n) {
    int i = blockIdx.x * blockDim.x + threadIdx.x;
    if (i < n) g_cnt[i] = 1;                    // self-loop
    if (i < 128) { g_sum[i] = 0.f; g_sq[i] = 0.f; }
    if (i == 0) g_barrier = 0;

    if (blockIdx.x == 0) {                      // int64-vs-int32 edge layout detect
        __shared__ int nz;
        if (threadIdx.x == 0) nz = 0;
        __syncthreads();
        if (ei[threadIdx.x * 2 + 1] != 0) atomicOr(&nz, 1);
        __syncthreads();
        if (threadIdx.x == 0) g_is64 = (nz == 0) ? 1 : 0;
    }

    if (i < 12288) {                            // weight fragment pack
        int lane  = i & 31;
        int ntile = (i >> 5) & 15;
        int kstep = (i >> 9) & 7;
        int set   = i >> 12;
        int nn = ntile * 8 + (lane >> 2);
        int k0 = kstep * 16 + (lane & 3) * 2;
        float w[4];
#pragma unroll
        for (int j = 0; j < 4; j++) {
            int k = k0 + (j & 1) + (j >> 1) * 8;
            float v;
            if (set == 0)      v = W1[k * 128 + nn];
            else if (set == 1) v = W2[k * 128 + nn];
            else               v = (nn < 64) ? Wmu[k * 64 + nn] : Wls[k * 64 + (nn - 64)];
            w[j] = v;
        }
        uint4 f;
        pack_hilo(w[0], w[1], f.x, f.z);
        pack_hilo(w[2], w[3], f.y, f.w);
        g_Bf[set][kstep * 512 + ntile * 32 + lane] = f;
    }
}

// ---------------- fused CSR build: count -> scan -> fill (grid-sync via spin) ----------------
__device__ __forceinline__ void gbar(int phase) {
    __syncthreads();
    __threadfence();
    if (threadIdx.x == 0) {
        atomicAdd(&g_barrier, 1);
        int target = phase * (int)gridDim.x;
        while (*(volatile int*)&g_barrier < target) __nanosleep(64);
    }
    __syncthreads();
}

__global__ void __launch_bounds__(256, 4) k_csr(const int* __restrict__ ei, int E, int n) {
    int tid = threadIdx.x, bid = blockIdx.x;
    int gt = bid * 256 + tid;
    int gsz = gridDim.x * 256;
    int is64 = g_is64;
    int lane = tid & 31, w = tid >> 5;
    __shared__ int wsum[8];

    for (int e = gt; e < E; e += gsz) {
        int d = is64 ? ei[2 * (E + e)] : ei[E + e];
        atomicAdd(&g_cnt[d], 1);
    }
    gbar(1);

    int i = gt;
    int v = (i < n) ? g_cnt[i] : 0;
    int x = v;
#pragma unroll
    for (int o = 1; o < 32; o <<= 1) {
        int y = __shfl_up_sync(0xffffffffu, x, o);
        if (lane >= o) x += y;
    }
    if (lane == 31) wsum[w] = x;
    __syncthreads();
    if (w == 0 && lane < 8) {
        int q = wsum[lane];
#pragma unroll
        for (int o = 1; o < 8; o <<= 1) {
            int y = __shfl_up_sync(0xffu, q, o);
            if (lane >= o) q += y;
        }
        wsum[lane] = q;
    }
    __syncthreads();
    int incl = x + (w ? wsum[w - 1] : 0);
    if (tid == 255) g_bsum[bid] = incl;
    gbar(2);

    if (bid == 0) {
        int nb = gridDim.x;
        int bv = (tid < nb) ? g_bsum[tid] : 0;
        int bx = bv;
#pragma unroll
        for (int o = 1; o < 32; o <<= 1) {
            int y = __shfl_up_sync(0xffffffffu, bx, o);
            if (lane >= o) bx += y;
        }
        if (lane == 31) wsum[w] = bx;
        __syncthreads();
        if (w == 0 && lane < 8) {
            int q = wsum[lane];
#pragma unroll
            for (int o = 1; o < 8; o <<= 1) {
                int y = __shfl_up_sync(0xffu, q, o);
                if (lane >= o) q += y;
            }
            wsum[lane] = q;
        }
        __syncthreads();
        int bincl = bx + (w ? wsum[w - 1] : 0);
        if (tid < nb) g_boff[tid] = bincl - bv;
    }
    gbar(3);

    if (i < n) {
        int rp = g_boff[bid] + incl - v;
        g_rowptr[i] = rp;
        g_fill[i] = rp;
        g_dinv[i] = rsqrtf((float)v);
    }
    if (gt == 0) g_rowptr[n] = n + E;
    gbar(4);

    int tot = E + n;
    for (int e = gt; e < tot; e += gsz) {
        int s, d;
        if (e < E) {
            if (is64) { s = ei[2 * e]; d = ei[2 * (E + e)]; }
            else      { s = ei[e];     d = ei[E + e]; }
        } else {
            s = d = e - E;
        }
        int pos = atomicAdd(&g_fill[d], 1);
        g_src[pos] = s;
    }
}

// ---------------- HMMA GEMM (N-split): h[:,ny*64..+64] = dinv * act(A) @ W ----------------
__device__ __forceinline__ void mma16816(float c[4], const uint32_t a[4],
                                         uint32_t b0, uint32_t b1) {
    asm volatile(
        "mma.sync.aligned.m16n8k16.row.col.f32.bf16.bf16.f32 "
        "{%0,%1,%2,%3}, {%4,%5,%6,%7}, {%8,%9}, {%0,%1,%2,%3};"
        : "+f"(c[0]), "+f"(c[1]), "+f"(c[2]), "+f"(c[3])
        : "r"(a[0]), "r"(a[1]), "r"(a[2]), "r"(a[3]), "r"(b0), "r"(b1));
}

#define GEMM_SMEM (32768 + 1024)
template <bool TR>
__global__ void __launch_bounds__(256) k_mgemm(const float* __restrict__ Aext,
                                               int set, int M) {
    extern __shared__ char sraw[];
    uint4* Bs = (uint4*)sraw;                        // 2048 x 16B = 32KB (8 ntiles)
    float* ssc = (float*)(sraw + 32768);
    float* ssh = ssc + 128;

    const float* A = Aext ? Aext : (const float*)g_agg;
    int t = threadIdx.x, lane = t & 31, w = t >> 5;
    int ny = blockIdx.y;                              // 0/1: which 64-col half

    {
        const uint4* src = &g_Bf[set][0];
#pragma unroll
        for (int i = 0; i < 8; i++) {
            int idx = t + i * 256;                    // 0..2047
            int ks = idx >> 8;                        // 0..7
            int r = idx & 255;                        // ntile(8)*32 + lane
            Bs[idx] = src[ks * 512 + ny * 256 + r];
        }
    }
    if (TR && t < 128) { ssc[t] = g_scale[t]; ssh[t] = g_shift[t]; }
    __syncthreads();

    int r0 = blockIdx.x * 128 + w * 16 + (lane >> 2);
    int r1 = r0 + 8;
    bool ok0 = r0 < M, ok1 = r1 < M;
    const float* a0p = A + (size_t)(ok0 ? r0 : 0) * 128;
    const float* a1p = A + (size_t)(ok1 ? r1 : 0) * 128;
    int kq = (lane & 3) * 2;

    float c[8][4];
#pragma unroll
    for (int nt = 0; nt < 8; nt++)
#pragma unroll
        for (int j = 0; j < 4; j++) c[nt][j] = 0.f;

#pragma unroll
    for (int ks = 0; ks < 8; ks++) {
        int k0 = ks * 16 + kq;
        float2 A00 = ok0 ? __ldg((const float2*)(a0p + k0))     : make_float2(0.f, 0.f);
        float2 A01 = ok0 ? __ldg((const float2*)(a0p + k0 + 8)) : make_float2(0.f, 0.f);
        float2 A10 = ok1 ? __ldg((const float2*)(a1p + k0))     : make_float2(0.f, 0.f);
        float2 A11 = ok1 ? __ldg((const float2*)(a1p + k0 + 8)) : make_float2(0.f, 0.f);
        if (TR) {
            float s0 = ssc[k0], s1 = ssc[k0 + 1], s8 = ssc[k0 + 8], s9 = ssc[k0 + 9];
            float h0 = ssh[k0], h1 = ssh[k0 + 1], h8 = ssh[k0 + 8], h9 = ssh[k0 + 9];
            A00.x = fmaxf(fmaf(A00.x, s0, h0), 0.f);
            A00.y = fmaxf(fmaf(A00.y, s1, h1), 0.f);
            A10.x = fmaxf(fmaf(A10.x, s0, h0), 0.f);
            A10.y = fmaxf(fmaf(A10.y, s1, h1), 0.f);
            A01.x = fmaxf(fmaf(A01.x, s8, h8), 0.f);
            A01.y = fmaxf(fmaf(A01.y, s9, h9), 0.f);
            A11.x = fmaxf(fmaf(A11.x, s8, h8), 0.f);
            A11.y = fmaxf(fmaf(A11.y, s9, h9), 0.f);
        }
        uint32_t ah[4], al[4];
        pack_hilo(A00.x, A00.y, ah[0], al[0]);
        pack_hilo(A10.x, A10.y, ah[1], al[1]);
        pack_hilo(A01.x, A01.y, ah[2], al[2]);
        pack_hilo(A11.x, A11.y, ah[3], al[3]);

        const uint4* brow = &Bs[ks * 256 + lane];
#pragma unroll
        for (int nt = 0; nt < 8; nt++) {
            uint4 bb = brow[nt * 32];
            mma16816(c[nt], ah, bb.x, bb.y);
            mma16816(c[nt], ah, bb.z, bb.w);
            mma16816(c[nt], al, bb.x, bb.y);
        }
    }

    float dv0 = ok0 ? __ldg(&g_dinv[r0]) : 0.f;
    float dv1 = ok1 ? __ldg(&g_dinv[r1]) : 0.f;

    float* out = (float*)g_h;
    int col0 = ny * 64 + (lane & 3) * 2;
#pragma unroll
    for (int nt = 0; nt < 8; nt++) {
        int n0 = col0 + nt * 8;
        if (ok0) *(float2*)&out[(size_t)r0 * 128 + n0] =
            make_float2(c[nt][0] * dv0, c[nt][1] * dv0);
        if (ok1) *(float2*)&out[(size_t)r1 * 128 + n0] =
            make_float2(c[nt][2] * dv1, c[nt][3] * dv1);
    }
}

// ---------------- gather drain helper (j..cnt of one 32-src batch) ----------------
__device__ __forceinline__ void drain(int sv, int j, int cnt, const float* __restrict__ hc,
                                      float& x0, float& x1, float& x2, float& x3) {
    for (; j + 4 <= cnt; j += 4) {
        int s0 = __shfl_sync(0xffffffffu, sv, j + 0);
        int s1 = __shfl_sync(0xffffffffu, sv, j + 1);
        int s2 = __shfl_sync(0xffffffffu, sv, j + 2);
        int s3 = __shfl_sync(0xffffffffu, sv, j + 3);
        float v0 = __ldg(hc + (size_t)s0 * 128);
        float v1 = __ldg(hc + (size_t)s1 * 128);
        float v2 = __ldg(hc + (size_t)s2 * 128);
        float v3 = __ldg(hc + (size_t)s3 * 128);
        x0 += v0; x1 += v1; x2 += v2; x3 += v3;
    }
    for (; j < cnt; j++) {
        int s = __shfl_sync(0xffffffffu, sv, j);
        x0 += __ldg(hc + (size_t)s * 128);
    }
}

// ---------------- CSR aggregation: channel-split + dual-node interleave (R11) ----------
// 4 warps per node range, each owns 32 channels (gather = 1 float/lane, 128B line).
// TWO nodes in flight per warp; next pair's metadata prefetched one iteration ahead.
template <bool BN, bool FINAL>
__global__ void __launch_bounds__(256) k_agg(float* __restrict__ dout,
                                             const float* __restrict__ bmu,
                                             const float* __restrict__ bls,
                                             int n) {
    const float* __restrict__ h = (const float*)g_h;
    const int* __restrict__ gs = g_src;
    int lane = threadIdx.x & 31;
    int gw = (blockIdx.x * blockDim.x + threadIdx.x) >> 5;
    int nw = (gridDim.x * blockDim.x) >> 5;     // 9472
    int grp = gw & 3;                            // channel group 0..3
    int rid = gw >> 2;                           // node-range id
    int nr = nw >> 2;                            // 2368 ranges
    int chunk = (n + nr - 1) / nr;               // ~22 nodes
    int i0 = rid * chunk;
    int i1 = min(n, i0 + chunk);
    int cb = grp * 32;
    const float* hc = h + cb + lane;             // + s*128 per gather

    float bsum = 0.f, bsq = 0.f;

    if (i0 < n) {
        int rp0 = __ldg(&g_rowptr[i0]);
        int rp1 = __ldg(&g_rowptr[i0 + 1]);
        bool tw0 = (i0 + 1 < i1);
        int rp2 = tw0 ? __ldg(&g_rowptr[i0 + 2]) : rp1;
        int sv0 = __ldg(&gs[min(rp0 + lane, ETOT - 1)]);
        int sv1 = tw0 ? __ldg(&gs[min(rp1 + lane, ETOT - 1)]) : 0;

        for (int i = i0; i < i1; i += 2) {
            bool two = (i + 1 < i1);
            int nrp0 = rp2, nrp1 = rp2, nrp2 = rp2, nsv0 = 0, nsv1 = 0;
            if (i + 2 < i1) {
                nrp1 = __ldg(&g_rowptr[i + 3]);
                nrp2 = (i + 3 < i1) ? __ldg(&g_rowptr[i + 4]) : nrp1;
                nsv0 = __ldg(&gs[min(nrp0 + lane, ETOT - 1)]);
                nsv1 = (i + 3 < i1) ? __ldg(&gs[min(nrp1 + lane, ETOT - 1)]) : 0;
            }

            int cnt0 = min(32, rp1 - rp0);
            int cnt1 = two ? min(32, rp2 - rp1) : 0;
            float a0 = 0.f, a1 = 0.f, a2 = 0.f, a3 = 0.f;
            float b0 = 0.f, b1 = 0.f, b2 = 0.f, b3 = 0.f;

            int m = min(cnt0, cnt1) & ~3;
            int j = 0;
            for (; j < m; j += 4) {
                int sA0 = __shfl_sync(0xffffffffu, sv0, j + 0);
                int sA1 = __shfl_sync(0xffffffffu, sv0, j + 1);
                int sA2 = __shfl_sync(0xffffffffu, sv0, j + 2);
                int sA3 = __shfl_sync(0xffffffffu, sv0, j + 3);
                int sB0 = __shfl_sync(0xffffffffu, sv1, j + 0);
                int sB1 = __shfl_sync(0xffffffffu, sv1, j + 1);
                int sB2 = __shfl_sync(0xffffffffu, sv1, j + 2);
                int sB3 = __shfl_sync(0xffffffffu, sv1, j + 3);
                float vA0 = __ldg(hc + (size_t)sA0 * 128);
                float vA1 = __ldg(hc + (size_t)sA1 * 128);
                float vA2 = __ldg(hc + (size_t)sA2 * 128);
                float vA3 = __ldg(hc + (size_t)sA3 * 128);
                float vB0 = __ldg(hc + (size_t)sB0 * 128);
                float vB1 = __ldg(hc + (size_t)sB1 * 128);
                float vB2 = __ldg(hc + (size_t)sB2 * 128);
                float vB3 = __ldg(hc + (size_t)sB3 * 128);
                a0 += vA0; a1 += vA1; a2 += vA2; a3 += vA3;
                b0 += vB0; b1 += vB1; b2 += vB2; b3 += vB3;
            }
            drain(sv0, j, cnt0, hc, a0, a1, a2, a3);
            if (two) drain(sv1, j, cnt1, hc, b0, b1, b2, b3);
            for (int base = rp0 + 32; base < rp1; base += 32) {
                int rem = rp1 - base;
                int sv2 = 0;
                if (lane < rem) sv2 = __ldg(&gs[base + lane]);
                drain(sv2, 0, min(32, rem), hc, a0, a1, a2, a3);
            }
            if (two) {
                for (int base = rp1 + 32; base < rp2; base += 32) {
                    int rem = rp2 - base;
                    int sv2 = 0;
                    if (lane < rem) sv2 = __ldg(&gs[base + lane]);
                    drain(sv2, 0, min(32, rem), hc, b0, b1, b2, b3);
                }
            }

            float accA = ((a0 + a1) + (a2 + a3)) * __ldg(&g_dinv[i]);
            float accB = two ? ((b0 + b1) + (b2 + b3)) * __ldg(&g_dinv[i + 1]) : 0.f;

            if (FINAL) {
                if (grp < 2) {
                    float b = __ldg(&bmu[cb + lane]);
                    dout[(size_t)i * 64 + cb + lane] = accA + b;
                    if (two) dout[(size_t)(i + 1) * 64 + cb + lane] = accB + b;
                } else {
                    float b = __ldg(&bls[cb - 64 + lane]);
                    dout[(size_t)n * 64 + (size_t)i * 64 + (cb - 64) + lane] = accA + b;
                    if (two)
                        dout[(size_t)n * 64 + (size_t)(i + 1) * 64 + (cb - 64) + lane] = accB + b;
                }
            } else {
                ((float*)g_agg)[(size_t)i * 128 + cb + lane] = accA;
                if (two) ((float*)g_agg)[(size_t)(i + 1) * 128 + cb + lane] = accB;
                if (BN) {
                    bsum += accA + accB;
                    bsq = fmaf(accA, accA, bsq);
                    bsq = fmaf(accB, accB, bsq);
                }
            }
            rp0 = nrp0; rp1 = nrp1; rp2 = nrp2; sv0 = nsv0; sv1 = nsv1;
        }
    }
    if (BN && !FINAL) {
        atomicAdd(&g_sum[cb + lane], bsum);
        atomicAdd(&g_sq[cb + lane], bsq);
    }
}

__global__ void k_bn(const float* __restrict__ gamma,
                     const float* __restrict__ beta, float invN) {
    int c = threadIdx.x;  // 128
    float mean = g_sum[c] * invN;
    float var = g_sq[c] * invN - mean * mean;
    float rs = rsqrtf(var + 1e-5f);
    float sc = gamma[c] * rs;
    g_scale[c] = sc;
    g_shift[c] = beta[c] - mean * sc;
    g_sum[c] = 0.f;
    g_sq[c] = 0.f;
}

// ---------------- launcher ----------------
extern "C" void kernel_launch(void* const* d_in, const int* in_sizes, int n_in,
                              void* d_out, int out_size) {
    const float* x   = (const float*)d_in[0];
    const int*   ei  = (const int*)d_in[1];
    const float* W1  = (const float*)d_in[2];
    const float* ga1 = (const float*)d_in[4];
    const float* be1 = (const float*)d_in[5];
    const float* W2  = (const float*)d_in[6];
    const float* ga2 = (const float*)d_in[8];
    const float* be2 = (const float*)d_in[9];
    const float* Wmu = (const float*)d_in[10];
    const float* bmu = (const float*)d_in[11];
    const float* Wls = (const float*)d_in[12];
    const float* bls = (const float*)d_in[13];

    int n = in_sizes[0] / 128;   // 50000
    int E = in_sizes[1] / 2;     // 800000
    float* outp = (float*)d_out;

    cudaFuncSetAttribute(k_mgemm<false>, cudaFuncAttributeMaxDynamicSharedMemorySize, GEMM_SMEM);
    cudaFuncSetAttribute(k_mgemm<true>,  cudaFuncAttributeMaxDynamicSharedMemorySize, GEMM_SMEM);

    dim3 gg((n + 127) / 128, 2);
    int nblk = (n + 255) / 256;   // 196

    k_setup<<<nblk, 256>>>(ei, W1, W2, Wmu, Wls, n);            // 1
    k_csr<<<nblk, 256>>>(ei, E, n);                             // 2
    k_mgemm<false><<<gg, 256, GEMM_SMEM>>>(x, 0, n);            // 3
    k_agg<true, false><<<1184, 256>>>(nullptr, nullptr, nullptr, n);  // 4 <- profiled
    k_bn<<<1, 128>>>(ga1, be1, 1.0f / n);

    k_mgemm<true><<<gg, 256, GEMM_SMEM>>>(nullptr, 1, n);
    k_agg<true, false><<<1184, 256>>>(nullptr, nullptr, nullptr, n);
    k_bn<<<1, 128>>>(ga2, be2, 1.0f / n);

    k_mgemm<true><<<gg, 256, GEMM_SMEM>>>(nullptr, 2, n);
    k_agg<false, true><<<1184, 256>>>(outp, bmu, bls, n);
}

// round 14
// speedup vs baseline: 1.1314x; 1.1314x over previous
#include <cuda_runtime.h>
#include <cuda_bf16.h>
#include <cstdint>

#define NN 50000
#define EE 800000
#define ETOT (NN + EE)

// ---------------- scratch (static device globals; no allocation) ----------------
__device__ float4 g_h[NN * 32];     // GEMM output, pre-scaled by dinv[row]  [N,128]
__device__ float4 g_agg[NN * 32];   // aggregated  [N,128]
__device__ __align__(16) int g_cnt[NN];
__device__ float  g_dinv[NN];
__device__ int    g_rowptr[NN + 1];
__device__ int    g_fill[NN];
__device__ int    g_src[ETOT];      // CSR src indices (norm folded into h / output)
__device__ float  g_sum[128], g_sq[128], g_scale[128], g_shift[128];
__device__ int    g_is64;
__device__ int    g_bsum[256], g_boff[256];
__device__ int    g_barrier;
__device__ uint4  g_Bf[3][4096];    // mma fragments [set][kstep(8)][ntile(16)][lane(32)]

// ---------------- bf16 hi/lo helpers ----------------
__device__ __forceinline__ void pack_hilo(float x, float y, uint32_t& h, uint32_t& l) {
    __nv_bfloat162 hb = __floats2bfloat162_rn(x, y);
    float hx = __bfloat162float(hb.x), hy = __bfloat162float(hb.y);
    __nv_bfloat162 lb = __floats2bfloat162_rn(x - hx, y - hy);
    h = *(uint32_t*)&hb;
    l = *(uint32_t*)&lb;
}

// ---------------- k_setup: init + detect + weight fragment pack ----------------
__global__ void __launch_bounds__(256) k_setup(
    const int* __restrict__ ei,
    const float* __restrict__ W1, const float* __restrict__ W2,
    const float* __restrict__ Wmu, const float* __restrict__ Wls, int n) {
    int i = blockIdx.x * blockDim.x + threadIdx.x;
    if (i < n) g_cnt[i] = 1;                    // self-loop
    if (i < 128) { g_sum[i] = 0.f; g_sq[i] = 0.f; }
    if (i == 0) g_barrier = 0;

    if (blockIdx.x == 0) {                      // int64-vs-int32 edge layout detect
        __shared__ int nz;
        if (threadIdx.x == 0) nz = 0;
        __syncthreads();
        if (ei[threadIdx.x * 2 + 1] != 0) atomicOr(&nz, 1);
        __syncthreads();
        if (threadIdx.x == 0) g_is64 = (nz == 0) ? 1 : 0;
    }

    if (i < 12288) {                            // weight fragment pack
        int lane  = i & 31;
        int ntile = (i >> 5) & 15;
        int kstep = (i >> 9) & 7;
        int set   = i >> 12;
        int nn = ntile * 8 + (lane >> 2);
        int k0 = kstep * 16 + (lane & 3) * 2;
        float w[4];
#pragma unroll
        for (int j = 0; j < 4; j++) {
            int k = k0 + (j & 1) + (j >> 1) * 8;
            float v;
            if (set == 0)      v = W1[k * 128 + nn];
            else if (set == 1) v = W2[k * 128 + nn];
            else               v = (nn < 64) ? Wmu[k * 64 + nn] : Wls[k * 64 + (nn - 64)];
            w[j] = v;
        }
        uint4 f;
        pack_hilo(w[0], w[1], f.x, f.z);
        pack_hilo(w[2], w[3], f.y, f.w);
        g_Bf[set][kstep * 512 + ntile * 32 + lane] = f;
    }
}

// ---------------- fused CSR build: count -> scan -> fill (grid-sync via spin) ----------------
__device__ __forceinline__ void gbar(int phase) {
    __syncthreads();
    __threadfence();
    if (threadIdx.x == 0) {
        atomicAdd(&g_barrier, 1);
        int target = phase * (int)gridDim.x;
        while (*(volatile int*)&g_barrier < target) __nanosleep(64);
    }
    __syncthreads();
}

__global__ void __launch_bounds__(256, 4) k_csr(const int* __restrict__ ei, int E, int n) {
    int tid = threadIdx.x, bid = blockIdx.x;
    int gt = bid * 256 + tid;
    int gsz = gridDim.x * 256;
    int is64 = g_is64;
    int lane = tid & 31, w = tid >> 5;
    __shared__ int wsum[8];

    for (int e = gt; e < E; e += gsz) {
        int d = is64 ? ei[2 * (E + e)] : ei[E + e];
        atomicAdd(&g_cnt[d], 1);
    }
    gbar(1);

    int i = gt;
    int v = (i < n) ? g_cnt[i] : 0;
    int x = v;
#pragma unroll
    for (int o = 1; o < 32; o <<= 1) {
        int y = __shfl_up_sync(0xffffffffu, x, o);
        if (lane >= o) x += y;
    }
    if (lane == 31) wsum[w] = x;
    __syncthreads();
    if (w == 0 && lane < 8) {
        int q = wsum[lane];
#pragma unroll
        for (int o = 1; o < 8; o <<= 1) {
            int y = __shfl_up_sync(0xffu, q, o);
            if (lane >= o) q += y;
        }
        wsum[lane] = q;
    }
    __syncthreads();
    int incl = x + (w ? wsum[w - 1] : 0);
    if (tid == 255) g_bsum[bid] = incl;
    gbar(2);

    if (bid == 0) {
        int nb = gridDim.x;
        int bv = (tid < nb) ? g_bsum[tid] : 0;
        int bx = bv;
#pragma unroll
        for (int o = 1; o < 32; o <<= 1) {
            int y = __shfl_up_sync(0xffffffffu, bx, o);
            if (lane >= o) bx += y;
        }
        if (lane == 31) wsum[w] = bx;
        __syncthreads();
        if (w == 0 && lane < 8) {
            int q = wsum[lane];
#pragma unroll
            for (int o = 1; o < 8; o <<= 1) {
                int y = __shfl_up_sync(0xffu, q, o);
                if (lane >= o) q += y;
            }
            wsum[lane] = q;
        }
        __syncthreads();
        int bincl = bx + (w ? wsum[w - 1] : 0);
        if (tid < nb) g_boff[tid] = bincl - bv;
    }
    gbar(3);

    if (i < n) {
        int rp = g_boff[bid] + incl - v;
        g_rowptr[i] = rp;
        g_fill[i] = rp;
        g_dinv[i] = rsqrtf((float)v);
    }
    if (gt == 0) g_rowptr[n] = n + E;
    gbar(4);

    int tot = E + n;
    for (int e = gt; e < tot; e += gsz) {
        int s, d;
        if (e < E) {
            if (is64) { s = ei[2 * e]; d = ei[2 * (E + e)]; }
            else      { s = ei[e];     d = ei[E + e]; }
        } else {
            s = d = e - E;
        }
        int pos = atomicAdd(&g_fill[d], 1);
        g_src[pos] = s;
    }
}

// ---------------- HMMA GEMM: h[M,128] = dinv[row] * act(A[M,128]) @ W[128,128] ----------------
__device__ __forceinline__ void mma16816(float c[4], const uint32_t a[4],
                                         uint32_t b0, uint32_t b1) {
    asm volatile(
        "mma.sync.aligned.m16n8k16.row.col.f32.bf16.bf16.f32 "
        "{%0,%1,%2,%3}, {%4,%5,%6,%7}, {%8,%9}, {%0,%1,%2,%3};"
        : "+f"(c[0]), "+f"(c[1]), "+f"(c[2]), "+f"(c[3])
        : "r"(a[0]), "r"(a[1]), "r"(a[2]), "r"(a[3]), "r"(b0), "r"(b1));
}

#define GEMM_SMEM (65536 + 1024)
template <bool TR>
__global__ void __launch_bounds__(256) k_mgemm(const float* __restrict__ Aext,
                                               int set, int M) {
    extern __shared__ char sraw[];
    uint4* Bs = (uint4*)sraw;
    float* ssc = (float*)(sraw + 65536);
    float* ssh = ssc + 128;

    const float* A = Aext ? Aext : (const float*)g_agg;
    int t = threadIdx.x, lane = t & 31, w = t >> 5;

    const uint4* src = &g_Bf[set][0];
#pragma unroll
    for (int i = 0; i < 16; i++) Bs[t + i * 256] = src[t + i * 256];
    if (TR && t < 128) { ssc[t] = g_scale[t]; ssh[t] = g_shift[t]; }
    __syncthreads();

    int r0 = blockIdx.x * 128 + w * 16 + (lane >> 2);
    int r1 = r0 + 8;
    bool ok0 = r0 < M, ok1 = r1 < M;
    const float* a0p = A + (size_t)(ok0 ? r0 : 0) * 128;
    const float* a1p = A + (size_t)(ok1 ? r1 : 0) * 128;
    int kq = (lane & 3) * 2;

    float c[16][4];
#pragma unroll
    for (int nt = 0; nt < 16; nt++)
#pragma unroll
        for (int j = 0; j < 4; j++) c[nt][j] = 0.f;

#pragma unroll
    for (int ks = 0; ks < 8; ks++) {
        int k0 = ks * 16 + kq;
        float2 A00 = ok0 ? __ldg((const float2*)(a0p + k0))     : make_float2(0.f, 0.f);
        float2 A01 = ok0 ? __ldg((const float2*)(a0p + k0 + 8)) : make_float2(0.f, 0.f);
        float2 A10 = ok1 ? __ldg((const float2*)(a1p + k0))     : make_float2(0.f, 0.f);
        float2 A11 = ok1 ? __ldg((const float2*)(a1p + k0 + 8)) : make_float2(0.f, 0.f);
        if (TR) {
            float s0 = ssc[k0], s1 = ssc[k0 + 1], s8 = ssc[k0 + 8], s9 = ssc[k0 + 9];
            float h0 = ssh[k0], h1 = ssh[k0 + 1], h8 = ssh[k0 + 8], h9 = ssh[k0 + 9];
            A00.x = fmaxf(fmaf(A00.x, s0, h0), 0.f);
            A00.y = fmaxf(fmaf(A00.y, s1, h1), 0.f);
            A10.x = fmaxf(fmaf(A10.x, s0, h0), 0.f);
            A10.y = fmaxf(fmaf(A10.y, s1, h1), 0.f);
            A01.x = fmaxf(fmaf(A01.x, s8, h8), 0.f);
            A01.y = fmaxf(fmaf(A01.y, s9, h9), 0.f);
            A11.x = fmaxf(fmaf(A11.x, s8, h8), 0.f);
            A11.y = fmaxf(fmaf(A11.y, s9, h9), 0.f);
        }
        uint32_t ah[4], al[4];
        pack_hilo(A00.x, A00.y, ah[0], al[0]);
        pack_hilo(A10.x, A10.y, ah[1], al[1]);
        pack_hilo(A01.x, A01.y, ah[2], al[2]);
        pack_hilo(A11.x, A11.y, ah[3], al[3]);

        const uint4* brow = &Bs[ks * 512 + lane];
#pragma unroll
        for (int nt = 0; nt < 16; nt++) {
            uint4 bb = brow[nt * 32];
            mma16816(c[nt], ah, bb.x, bb.y);
            mma16816(c[nt], ah, bb.z, bb.w);
            mma16816(c[nt], al, bb.x, bb.y);
        }
    }

    float dv0 = ok0 ? __ldg(&g_dinv[r0]) : 0.f;
    float dv1 = ok1 ? __ldg(&g_dinv[r1]) : 0.f;

    float* out = (float*)g_h;
    int col0 = (lane & 3) * 2;
#pragma unroll
    for (int nt = 0; nt < 16; nt++) {
        int n0 = nt * 8 + col0;
        if (ok0) *(float2*)&out[(size_t)r0 * 128 + n0] =
            make_float2(c[nt][0] * dv0, c[nt][1] * dv0);
        if (ok1) *(float2*)&out[(size_t)r1 * 128 + n0] =
            make_float2(c[nt][2] * dv1, c[nt][3] * dv1);
    }
}

// ---------------- batch-of-32 gather/accumulate helper ----------------
__device__ __forceinline__ void agg_batch(int sv, int cnt, const float* __restrict__ hc,
                                          float& a0, float& a1, float& a2, float& a3) {
    int j = 0;
    for (; j + 8 <= cnt; j += 8) {
        int s0 = __shfl_sync(0xffffffffu, sv, j + 0);
        int s1 = __shfl_sync(0xffffffffu, sv, j + 1);
        int s2 = __shfl_sync(0xffffffffu, sv, j + 2);
        int s3 = __shfl_sync(0xffffffffu, sv, j + 3);
        int s4 = __shfl_sync(0xffffffffu, sv, j + 4);
        int s5 = __shfl_sync(0xffffffffu, sv, j + 5);
        int s6 = __shfl_sync(0xffffffffu, sv, j + 6);
        int s7 = __shfl_sync(0xffffffffu, sv, j + 7);
        float v0 = __ldg(hc + (size_t)s0 * 128);
        float v1 = __ldg(hc + (size_t)s1 * 128);
        float v2 = __ldg(hc + (size_t)s2 * 128);
        float v3 = __ldg(hc + (size_t)s3 * 128);
        float v4 = __ldg(hc + (size_t)s4 * 128);
        float v5 = __ldg(hc + (size_t)s5 * 128);
        float v6 = __ldg(hc + (size_t)s6 * 128);
        float v7 = __ldg(hc + (size_t)s7 * 128);
        a0 += v0; a1 += v1; a2 += v2; a3 += v3;
        a0 += v4; a1 += v5; a2 += v6; a3 += v7;
    }
    for (; j < cnt; j++) {
        int s = __shfl_sync(0xffffffffu, sv, j);
        a0 += __ldg(hc + (size_t)s * 128);
    }
}

// ---------------- CSR aggregation (R10 design) @ tail-free occupancy ----------
// 4 warps per node range, each owns 32 channels (gather = 1 float/lane, 128B line).
// Next node's metadata prefetched one iteration ahead. Grid = 6 CTAs/SM x 148 SMs
// = 888 blocks (single wave, no tail); launch_bounds(256,6) caps regs at 42.
template <bool BN, bool FINAL>
__global__ void __launch_bounds__(256, 6) k_agg(float* __restrict__ dout,
                                                const float* __restrict__ bmu,
                                                const float* __restrict__ bls,
                                                int n) {
    const float* __restrict__ h = (const float*)g_h;
    const int* __restrict__ gs = g_src;
    int lane = threadIdx.x & 31;
    int gw = (blockIdx.x * blockDim.x + threadIdx.x) >> 5;
    int nw = (gridDim.x * blockDim.x) >> 5;     // 7104
    int grp = gw & 3;                            // channel group 0..3
    int rid = gw >> 2;                           // node-range id
    int nr = nw >> 2;                            // 1776 ranges
    int chunk = (n + nr - 1) / nr;               // ~29 nodes
    int i0 = rid * chunk;
    int i1 = min(n, i0 + chunk);
    int cb = grp * 32;
    const float* hc = h + cb + lane;             // + s*128 per gather

    float bsum = 0.f, bsq = 0.f;

    if (i0 < n) {
        int beg = __ldg(&g_rowptr[i0]);
        int end = __ldg(&g_rowptr[i0 + 1]);
        int sv = __ldg(&gs[min(beg + lane, ETOT - 1)]);   // first batch of node i0

        for (int i = i0; i < i1; i++) {
            // prefetch next node's metadata before consuming current gathers
            int nbeg = end, nend = end, nsv = 0;
            if (i + 1 < i1) {
                nend = __ldg(&g_rowptr[i + 2]);
                nsv = __ldg(&gs[min(nbeg + lane, ETOT - 1)]);
            }

            float a0 = 0.f, a1 = 0.f, a2 = 0.f, a3 = 0.f;
            agg_batch(sv, min(32, end - beg), hc, a0, a1, a2, a3);
            for (int base = beg + 32; base < end; base += 32) {   // rare: deg > 32
                int rem = end - base;
                int sv2 = 0;
                if (lane < rem) sv2 = __ldg(&gs[base + lane]);
                agg_batch(sv2, min(32, rem), hc, a0, a1, a2, a3);
            }

            float acc = ((a0 + a1) + (a2 + a3)) * __ldg(&g_dinv[i]);
            if (FINAL) {
                if (grp < 2) {
                    dout[(size_t)i * 64 + cb + lane] = acc + __ldg(&bmu[cb + lane]);
                } else {
                    dout[(size_t)n * 64 + (size_t)i * 64 + (cb - 64) + lane] =
                        acc + __ldg(&bls[cb - 64 + lane]);
                }
            } else {
                ((float*)g_agg)[(size_t)i * 128 + cb + lane] = acc;
                if (BN) { bsum += acc; bsq = fmaf(acc, acc, bsq); }
            }
            beg = nbeg; end = nend; sv = nsv;
        }
    }
    if (BN && !FINAL) {
        atomicAdd(&g_sum[cb + lane], bsum);
        atomicAdd(&g_sq[cb + lane], bsq);
    }
}

__global__ void k_bn(const float* __restrict__ gamma,
                     const float* __restrict__ beta, float invN) {
    int c = threadIdx.x;  // 128
    float mean = g_sum[c] * invN;
    float var = g_sq[c] * invN - mean * mean;
    float rs = rsqrtf(var + 1e-5f);
    float sc = gamma[c] * rs;
    g_scale[c] = sc;
    g_shift[c] = beta[c] - mean * sc;
    g_sum[c] = 0.f;
    g_sq[c] = 0.f;
}

// ---------------- launcher ----------------
extern "C" void kernel_launch(void* const* d_in, const int* in_sizes, int n_in,
                              void* d_out, int out_size) {
    const float* x   = (const float*)d_in[0];
    const int*   ei  = (const int*)d_in[1];
    const float* W1  = (const float*)d_in[2];
    const float* ga1 = (const float*)d_in[4];
    const float* be1 = (const float*)d_in[5];
    const float* W2  = (const float*)d_in[6];
    const float* ga2 = (const float*)d_in[8];
    const float* be2 = (const float*)d_in[9];
    const float* Wmu = (const float*)d_in[10];
    const float* bmu = (const float*)d_in[11];
    const float* Wls = (const float*)d_in[12];
    const float* bls = (const float*)d_in[13];

    int n = in_sizes[0] / 128;   // 50000
    int E = in_sizes[1] / 2;     // 800000
    float* outp = (float*)d_out;

    cudaFuncSetAttribute(k_mgemm<false>, cudaFuncAttributeMaxDynamicSharedMemorySize, GEMM_SMEM);
    cudaFuncSetAttribute(k_mgemm<true>,  cudaFuncAttributeMaxDynamicSharedMemorySize, GEMM_SMEM);

    int gb = (n + 127) / 128;
    int nblk = (n + 255) / 256;   // 196
    const int AGG_BLOCKS = 888;   // 6 CTAs/SM x 148 SMs: one full wave, no tail

    k_setup<<<nblk, 256>>>(ei, W1, W2, Wmu, Wls, n);            // 1
    k_csr<<<nblk, 256>>>(ei, E, n);                             // 2
    k_mgemm<false><<<gb, 256, GEMM_SMEM>>>(x, 0, n);            // 3
    k_agg<true, false><<<AGG_BLOCKS, 256>>>(nullptr, nullptr, nullptr, n);  // 4 <- profiled
    k_bn<<<1, 128>>>(ga1, be1, 1.0f / n);

    k_mgemm<true><<<gb, 256, GEMM_SMEM>>>(nullptr, 1, n);
    k_agg<true, false><<<AGG_BLOCKS, 256>>>(nullptr, nullptr, nullptr, n);
    k_bn<<<1, 128>>>(ga2, be2, 1.0f / n);

    k_mgemm<true><<<gb, 256, GEMM_SMEM>>>(nullptr, 2, n);
    k_agg<false, true><<<AGG_BLOCKS, 256>>>(outp, bmu, bls, n);
}

// round 15
// speedup vs baseline: 1.1400x; 1.0076x over previous
#include <cuda_runtime.h>
#include <cuda_bf16.h>
#include <cstdint>

#define NN 50000
#define EE 800000
#define ETOT (NN + EE)

// ---------------- scratch (static device globals; no allocation) ----------------
__device__ float4 g_h[NN * 32];     // GEMM output, pre-scaled by dinv[row]  [N,128]
__device__ float4 g_agg[NN * 32];   // aggregated  [N,128]
__device__ __align__(16) int g_cnt[NN];
__device__ float  g_dinv[NN];
__device__ int    g_rowptr[NN + 1];
__device__ int    g_fill[NN];
__device__ int    g_src[ETOT];      // CSR src indices (norm folded into h / output)
__device__ float  g_sum[128], g_sq[128], g_scale[128], g_shift[128];
__device__ int    g_is64;
__device__ int    g_bsum[256], g_boff[256];
__device__ int    g_barrier;
__device__ uint4  g_Bf[3][4096];    // mma fragments [set][kstep(8)][ntile(16)][lane(32)]

// ---------------- bf16 hi/lo helpers ----------------
__device__ __forceinline__ void pack_hilo(float x, float y, uint32_t& h, uint32_t& l) {
    __nv_bfloat162 hb = __floats2bfloat162_rn(x, y);
    float hx = __bfloat162float(hb.x), hy = __bfloat162float(hb.y);
    __nv_bfloat162 lb = __floats2bfloat162_rn(x - hx, y - hy);
    h = *(uint32_t*)&hb;
    l = *(uint32_t*)&lb;
}

// ---------------- k_setup: init + detect + weight fragment pack ----------------
__global__ void __launch_bounds__(256) k_setup(
    const int* __restrict__ ei,
    const float* __restrict__ W1, const float* __restrict__ W2,
    const float* __restrict__ Wmu, const float* __restrict__ Wls, int n) {
    int i = blockIdx.x * blockDim.x + threadIdx.x;
    if (i < n) g_cnt[i] = 1;                    // self-loop
    if (i < 128) { g_sum[i] = 0.f; g_sq[i] = 0.f; }
    if (i == 0) g_barrier = 0;

    if (blockIdx.x == 0) {                      // int64-vs-int32 edge layout detect
        __shared__ int nz;
        if (threadIdx.x == 0) nz = 0;
        __syncthreads();
        if (ei[threadIdx.x * 2 + 1] != 0) atomicOr(&nz, 1);
        __syncthreads();
        if (threadIdx.x == 0) g_is64 = (nz == 0) ? 1 : 0;
    }

    if (i < 12288) {                            // weight fragment pack
        int lane  = i & 31;
        int ntile = (i >> 5) & 15;
        int kstep = (i >> 9) & 7;
        int set   = i >> 12;
        int nn = ntile * 8 + (lane >> 2);
        int k0 = kstep * 16 + (lane & 3) * 2;
        float w[4];
#pragma unroll
        for (int j = 0; j < 4; j++) {
            int k = k0 + (j & 1) + (j >> 1) * 8;
            float v;
            if (set == 0)      v = W1[k * 128 + nn];
            else if (set == 1) v = W2[k * 128 + nn];
            else               v = (nn < 64) ? Wmu[k * 64 + nn] : Wls[k * 64 + (nn - 64)];
            w[j] = v;
        }
        uint4 f;
        pack_hilo(w[0], w[1], f.x, f.z);
        pack_hilo(w[2], w[3], f.y, f.w);
        g_Bf[set][kstep * 512 + ntile * 32 + lane] = f;
    }
}

// ---------------- fused CSR build: count -> scan -> fill (grid-sync via spin) ----------------
__device__ __forceinline__ void gbar(int phase) {
    __syncthreads();
    __threadfence();
    if (threadIdx.x == 0) {
        atomicAdd(&g_barrier, 1);
        int target = phase * (int)gridDim.x;
        while (*(volatile int*)&g_barrier < target) __nanosleep(64);
    }
    __syncthreads();
}

__global__ void __launch_bounds__(256, 4) k_csr(const int* __restrict__ ei, int E, int n) {
    int tid = threadIdx.x, bid = blockIdx.x;
    int gt = bid * 256 + tid;
    int gsz = gridDim.x * 256;
    int is64 = g_is64;
    int lane = tid & 31, w = tid >> 5;
    __shared__ int wsum[8];

    for (int e = gt; e < E; e += gsz) {
        int d = is64 ? ei[2 * (E + e)] : ei[E + e];
        atomicAdd(&g_cnt[d], 1);
    }
    gbar(1);

    int i = gt;
    int v = (i < n) ? g_cnt[i] : 0;
    int x = v;
#pragma unroll
    for (int o = 1; o < 32; o <<= 1) {
        int y = __shfl_up_sync(0xffffffffu, x, o);
        if (lane >= o) x += y;
    }
    if (lane == 31) wsum[w] = x;
    __syncthreads();
    if (w == 0 && lane < 8) {
        int q = wsum[lane];
#pragma unroll
        for (int o = 1; o < 8; o <<= 1) {
            int y = __shfl_up_sync(0xffu, q, o);
            if (lane >= o) q += y;
        }
        wsum[lane] = q;
    }
    __syncthreads();
    int incl = x + (w ? wsum[w - 1] : 0);
    if (tid == 255) g_bsum[bid] = incl;
    gbar(2);

    if (bid == 0) {
        int nb = gridDim.x;
        int bv = (tid < nb) ? g_bsum[tid] : 0;
        int bx = bv;
#pragma unroll
        for (int o = 1; o < 32; o <<= 1) {
            int y = __shfl_up_sync(0xffffffffu, bx, o);
            if (lane >= o) bx += y;
        }
        if (lane == 31) wsum[w] = bx;
        __syncthreads();
        if (w == 0 && lane < 8) {
            int q = wsum[lane];
#pragma unroll
            for (int o = 1; o < 8; o <<= 1) {
                int y = __shfl_up_sync(0xffu, q, o);
                if (lane >= o) q += y;
            }
            wsum[lane] = q;
        }
        __syncthreads();
        int bincl = bx + (w ? wsum[w - 1] : 0);
        if (tid < nb) g_boff[tid] = bincl - bv;
    }
    gbar(3);

    if (i < n) {
        int rp = g_boff[bid] + incl - v;
        g_rowptr[i] = rp;
        g_fill[i] = rp;
        g_dinv[i] = rsqrtf((float)v);
    }
    if (gt == 0) g_rowptr[n] = n + E;
    gbar(4);

    int tot = E + n;
    for (int e = gt; e < tot; e += gsz) {
        int s, d;
        if (e < E) {
            if (is64) { s = ei[2 * e]; d = ei[2 * (E + e)]; }
            else      { s = ei[e];     d = ei[E + e]; }
        } else {
            s = d = e - E;
        }
        int pos = atomicAdd(&g_fill[d], 1);
        g_src[pos] = s;
    }
}

// ---------------- persistent HMMA GEMM: h = dinv[row] * act(A) @ W ----------------
__device__ __forceinline__ void mma16816(float c[4], const uint32_t a[4],
                                         uint32_t b0, uint32_t b1) {
    asm volatile(
        "mma.sync.aligned.m16n8k16.row.col.f32.bf16.bf16.f32 "
        "{%0,%1,%2,%3}, {%4,%5,%6,%7}, {%8,%9}, {%0,%1,%2,%3};"
        : "+f"(c[0]), "+f"(c[1]), "+f"(c[2]), "+f"(c[3])
        : "r"(a[0]), "r"(a[1]), "r"(a[2]), "r"(a[3]), "r"(b0), "r"(b1));
}

#define GEMM_SMEM (65536 + 1024)
template <bool TR>
__global__ void __launch_bounds__(256) k_mgemm(const float* __restrict__ Aext,
                                               int set, int M) {
    extern __shared__ char sraw[];
    uint4* Bs = (uint4*)sraw;
    float* ssc = (float*)(sraw + 65536);
    float* ssh = ssc + 128;

    const float* A = Aext ? Aext : (const float*)g_agg;
    int t = threadIdx.x, lane = t & 31, w = t >> 5;

    const uint4* src = &g_Bf[set][0];
#pragma unroll
    for (int i = 0; i < 16; i++) Bs[t + i * 256] = src[t + i * 256];
    if (TR && t < 128) { ssc[t] = g_scale[t]; ssh[t] = g_shift[t]; }
    __syncthreads();

    int ntiles = (M + 127) >> 7;
    int kq = (lane & 3) * 2;
    float* out = (float*)g_h;
    int col0 = (lane & 3) * 2;

    for (int tile = blockIdx.x; tile < ntiles; tile += gridDim.x) {
        int r0 = tile * 128 + w * 16 + (lane >> 2);
        int r1 = r0 + 8;
        bool ok0 = r0 < M, ok1 = r1 < M;
        const float* a0p = A + (size_t)(ok0 ? r0 : 0) * 128;
        const float* a1p = A + (size_t)(ok1 ? r1 : 0) * 128;

        float c[16][4];
#pragma unroll
        for (int nt = 0; nt < 16; nt++)
#pragma unroll
            for (int j = 0; j < 4; j++) c[nt][j] = 0.f;

#pragma unroll
        for (int ks = 0; ks < 8; ks++) {
            int k0 = ks * 16 + kq;
            float2 A00 = ok0 ? __ldg((const float2*)(a0p + k0))     : make_float2(0.f, 0.f);
            float2 A01 = ok0 ? __ldg((const float2*)(a0p + k0 + 8)) : make_float2(0.f, 0.f);
            float2 A10 = ok1 ? __ldg((const float2*)(a1p + k0))     : make_float2(0.f, 0.f);
            float2 A11 = ok1 ? __ldg((const float2*)(a1p + k0 + 8)) : make_float2(0.f, 0.f);
            if (TR) {
                float s0 = ssc[k0], s1 = ssc[k0 + 1], s8 = ssc[k0 + 8], s9 = ssc[k0 + 9];
                float h0 = ssh[k0], h1 = ssh[k0 + 1], h8 = ssh[k0 + 8], h9 = ssh[k0 + 9];
                A00.x = fmaxf(fmaf(A00.x, s0, h0), 0.f);
                A00.y = fmaxf(fmaf(A00.y, s1, h1), 0.f);
                A10.x = fmaxf(fmaf(A10.x, s0, h0), 0.f);
                A10.y = fmaxf(fmaf(A10.y, s1, h1), 0.f);
                A01.x = fmaxf(fmaf(A01.x, s8, h8), 0.f);
                A01.y = fmaxf(fmaf(A01.y, s9, h9), 0.f);
                A11.x = fmaxf(fmaf(A11.x, s8, h8), 0.f);
                A11.y = fmaxf(fmaf(A11.y, s9, h9), 0.f);
            }
            uint32_t ah[4], al[4];
            pack_hilo(A00.x, A00.y, ah[0], al[0]);
            pack_hilo(A10.x, A10.y, ah[1], al[1]);
            pack_hilo(A01.x, A01.y, ah[2], al[2]);
            pack_hilo(A11.x, A11.y, ah[3], al[3]);

            const uint4* brow = &Bs[ks * 512 + lane];
#pragma unroll
            for (int nt = 0; nt < 16; nt++) {
                uint4 bb = brow[nt * 32];
                mma16816(c[nt], ah, bb.x, bb.y);
                mma16816(c[nt], ah, bb.z, bb.w);
                mma16816(c[nt], al, bb.x, bb.y);
            }
        }

        float dv0 = ok0 ? __ldg(&g_dinv[r0]) : 0.f;
        float dv1 = ok1 ? __ldg(&g_dinv[r1]) : 0.f;
#pragma unroll
        for (int nt = 0; nt < 16; nt++) {
            int n0 = nt * 8 + col0;
            if (ok0) *(float2*)&out[(size_t)r0 * 128 + n0] =
                make_float2(c[nt][0] * dv0, c[nt][1] * dv0);
            if (ok1) *(float2*)&out[(size_t)r1 * 128 + n0] =
                make_float2(c[nt][2] * dv1, c[nt][3] * dv1);
        }
    }
}

// ---------------- gather drain helper (j..cnt of one 32-src batch) ----------------
__device__ __forceinline__ void drain(int sv, int j, int cnt, const float* __restrict__ hc,
                                      float& x0, float& x1, float& x2, float& x3) {
    for (; j + 4 <= cnt; j += 4) {
        int s0 = __shfl_sync(0xffffffffu, sv, j + 0);
        int s1 = __shfl_sync(0xffffffffu, sv, j + 1);
        int s2 = __shfl_sync(0xffffffffu, sv, j + 2);
        int s3 = __shfl_sync(0xffffffffu, sv, j + 3);
        float v0 = __ldg(hc + (size_t)s0 * 128);
        float v1 = __ldg(hc + (size_t)s1 * 128);
        float v2 = __ldg(hc + (size_t)s2 * 128);
        float v3 = __ldg(hc + (size_t)s3 * 128);
        x0 += v0; x1 += v1; x2 += v2; x3 += v3;
    }
    for (; j < cnt; j++) {
        int s = __shfl_sync(0xffffffffu, sv, j);
        x0 += __ldg(hc + (size_t)s * 128);
    }
}

// ---------------- CSR aggregation: channel-split + dual-node interleave ----------
// 4 warps per node range, each owns 32 channels (single-line 128B gathers).
// TWO nodes in flight per warp; next pair's metadata prefetched one iteration
// ahead. Grid = 5 CTAs/SM x 148 = 740 blocks: tail-free and no reg spill (48 regs).
template <bool BN, bool FINAL>
__global__ void __launch_bounds__(256, 5) k_agg(float* __restrict__ dout,
                                                const float* __restrict__ bmu,
                                                const float* __restrict__ bls,
                                                int n) {
    const float* __restrict__ h = (const float*)g_h;
    const int* __restrict__ gs = g_src;
    int lane = threadIdx.x & 31;
    int gw = (blockIdx.x * blockDim.x + threadIdx.x) >> 5;
    int nw = (gridDim.x * blockDim.x) >> 5;     // 5920
    int grp = gw & 3;                            // channel group 0..3
    int rid = gw >> 2;                           // node-range id
    int nr = nw >> 2;                            // 1480 ranges
    int chunk = (n + nr - 1) / nr;               // ~34 nodes
    int i0 = rid * chunk;
    int i1 = min(n, i0 + chunk);
    int cb = grp * 32;
    const float* hc = h + cb + lane;             // + s*128 per gather

    float bsum = 0.f, bsq = 0.f;

    if (i0 < n) {
        int rp0 = __ldg(&g_rowptr[i0]);
        int rp1 = __ldg(&g_rowptr[i0 + 1]);
        bool tw0 = (i0 + 1 < i1);
        int rp2 = tw0 ? __ldg(&g_rowptr[i0 + 2]) : rp1;
        int sv0 = __ldg(&gs[min(rp0 + lane, ETOT - 1)]);
        int sv1 = tw0 ? __ldg(&gs[min(rp1 + lane, ETOT - 1)]) : 0;

        for (int i = i0; i < i1; i += 2) {
            bool two = (i + 1 < i1);
            int nrp0 = rp2, nrp1 = rp2, nrp2 = rp2, nsv0 = 0, nsv1 = 0;
            if (i + 2 < i1) {
                nrp1 = __ldg(&g_rowptr[i + 3]);
                nrp2 = (i + 3 < i1) ? __ldg(&g_rowptr[i + 4]) : nrp1;
                nsv0 = __ldg(&gs[min(nrp0 + lane, ETOT - 1)]);
                nsv1 = (i + 3 < i1) ? __ldg(&gs[min(nrp1 + lane, ETOT - 1)]) : 0;
            }

            int cnt0 = min(32, rp1 - rp0);
            int cnt1 = two ? min(32, rp2 - rp1) : 0;
            float a0 = 0.f, a1 = 0.f, a2 = 0.f, a3 = 0.f;
            float b0 = 0.f, b1 = 0.f, b2 = 0.f, b3 = 0.f;

            int m = min(cnt0, cnt1) & ~3;
            int j = 0;
            for (; j < m; j += 4) {
                int sA0 = __shfl_sync(0xffffffffu, sv0, j + 0);
                int sA1 = __shfl_sync(0xffffffffu, sv0, j + 1);
                int sA2 = __shfl_sync(0xffffffffu, sv0, j + 2);
                int sA3 = __shfl_sync(0xffffffffu, sv0, j + 3);
                int sB0 = __shfl_sync(0xffffffffu, sv1, j + 0);
                int sB1 = __shfl_sync(0xffffffffu, sv1, j + 1);
                int sB2 = __shfl_sync(0xffffffffu, sv1, j + 2);
                int sB3 = __shfl_sync(0xffffffffu, sv1, j + 3);
                float vA0 = __ldg(hc + (size_t)sA0 * 128);
                float vA1 = __ldg(hc + (size_t)sA1 * 128);
                float vA2 = __ldg(hc + (size_t)sA2 * 128);
                float vA3 = __ldg(hc + (size_t)sA3 * 128);
                float vB0 = __ldg(hc + (size_t)sB0 * 128);
                float vB1 = __ldg(hc + (size_t)sB1 * 128);
                float vB2 = __ldg(hc + (size_t)sB2 * 128);
                float vB3 = __ldg(hc + (size_t)sB3 * 128);
                a0 += vA0; a1 += vA1; a2 += vA2; a3 += vA3;
                b0 += vB0; b1 += vB1; b2 += vB2; b3 += vB3;
            }
            drain(sv0, j, cnt0, hc, a0, a1, a2, a3);
            if (two) drain(sv1, j, cnt1, hc, b0, b1, b2, b3);
            for (int base = rp0 + 32; base < rp1; base += 32) {
                int rem = rp1 - base;
                int sv2 = 0;
                if (lane < rem) sv2 = __ldg(&gs[base + lane]);
                drain(sv2, 0, min(32, rem), hc, a0, a1, a2, a3);
            }
            if (two) {
                for (int base = rp1 + 32; base < rp2; base += 32) {
                    int rem = rp2 - base;
                    int sv2 = 0;
                    if (lane < rem) sv2 = __ldg(&gs[base + lane]);
                    drain(sv2, 0, min(32, rem), hc, b0, b1, b2, b3);
                }
            }

            float accA = ((a0 + a1) + (a2 + a3)) * __ldg(&g_dinv[i]);
            float accB = two ? ((b0 + b1) + (b2 + b3)) * __ldg(&g_dinv[i + 1]) : 0.f;

            if (FINAL) {
                if (grp < 2) {
                    float b = __ldg(&bmu[cb + lane]);
                    dout[(size_t)i * 64 + cb + lane] = accA + b;
                    if (two) dout[(size_t)(i + 1) * 64 + cb + lane] = accB + b;
                } else {
                    float b = __ldg(&bls[cb - 64 + lane]);
                    dout[(size_t)n * 64 + (size_t)i * 64 + (cb - 64) + lane] = accA + b;
                    if (two)
                        dout[(size_t)n * 64 + (size_t)(i + 1) * 64 + (cb - 64) + lane] = accB + b;
                }
            } else {
                ((float*)g_agg)[(size_t)i * 128 + cb + lane] = accA;
                if (two) ((float*)g_agg)[(size_t)(i + 1) * 128 + cb + lane] = accB;
                if (BN) {
                    bsum += accA + accB;
                    bsq = fmaf(accA, accA, bsq);
                    bsq = fmaf(accB, accB, bsq);
                }
            }
            rp0 = nrp0; rp1 = nrp1; rp2 = nrp2; sv0 = nsv0; sv1 = nsv1;
        }
    }
    if (BN && !FINAL) {
        atomicAdd(&g_sum[cb + lane], bsum);
        atomicAdd(&g_sq[cb + lane], bsq);
    }
}

__global__ void k_bn(const float* __restrict__ gamma,
                     const float* __restrict__ beta, float invN) {
    int c = threadIdx.x;  // 128
    float mean = g_sum[c] * invN;
    float var = g_sq[c] * invN - mean * mean;
    float rs = rsqrtf(var + 1e-5f);
    float sc = gamma[c] * rs;
    g_scale[c] = sc;
    g_shift[c] = beta[c] - mean * sc;
    g_sum[c] = 0.f;
    g_sq[c] = 0.f;
}

// ---------------- launcher ----------------
extern "C" void kernel_launch(void* const* d_in, const int* in_sizes, int n_in,
                              void* d_out, int out_size) {
    const float* x   = (const float*)d_in[0];
    const int*   ei  = (const int*)d_in[1];
    const float* W1  = (const float*)d_in[2];
    const float* ga1 = (const float*)d_in[4];
    const float* be1 = (const float*)d_in[5];
    const float* W2  = (const float*)d_in[6];
    const float* ga2 = (const float*)d_in[8];
    const float* be2 = (const float*)d_in[9];
    const float* Wmu = (const float*)d_in[10];
    const float* bmu = (const float*)d_in[11];
    const float* Wls = (const float*)d_in[12];
    const float* bls = (const float*)d_in[13];

    int n = in_sizes[0] / 128;   // 50000
    int E = in_sizes[1] / 2;     // 800000
    float* outp = (float*)d_out;

    cudaFuncSetAttribute(k_mgemm<false>, cudaFuncAttributeMaxDynamicSharedMemorySize, GEMM_SMEM);
    cudaFuncSetAttribute(k_mgemm<true>,  cudaFuncAttributeMaxDynamicSharedMemorySize, GEMM_SMEM);

    int nblk = (n + 255) / 256;     // 196
    const int GEMM_BLOCKS = 296;    // 2 CTAs/SM x 148 SMs, persistent over row tiles
    const int AGG_BLOCKS = 740;     // 5 CTAs/SM x 148 SMs, tail-free, no reg spill

    k_setup<<<nblk, 256>>>(ei, W1, W2, Wmu, Wls, n);            // 1
    k_csr<<<nblk, 256>>>(ei, E, n);                             // 2
    k_mgemm<false><<<GEMM_BLOCKS, 256, GEMM_SMEM>>>(x, 0, n);   // 3
    k_agg<true, false><<<AGG_BLOCKS, 256>>>(nullptr, nullptr, nullptr, n);  // 4 <- profiled
    k_bn<<<1, 128>>>(ga1, be1, 1.0f / n);

    k_mgemm<true><<<GEMM_BLOCKS, 256, GEMM_SMEM>>>(nullptr, 1, n);
    k_agg<true, false><<<AGG_BLOCKS, 256>>>(nullptr, nullptr, nullptr, n);
    k_bn<<<1, 128>>>(ga2, be2, 1.0f / n);

    k_mgemm<true><<<GEMM_BLOCKS, 256, GEMM_SMEM>>>(nullptr, 2, n);
    k_agg<false, true><<<AGG_BLOCKS, 256>>>(outp, bmu, bls, n);
}